// round 1
// baseline (speedup 1.0000x reference)
#include <cuda_runtime.h>

#define B_ 4
#define H_ 16
#define T_ 2048
#define K_ 64
#define CH_ 128
#define N_ 16              // chunks per sequence
#define BH_ (B_*H_)        // 64
#define OUT_ELEMS (B_*H_*T_*K_)   // 8388608

#define LOGMIN (-5.2983174324035645f)   // log(0.005)

// ---- scratch (device globals: no allocations allowed) ----
__device__ float g_rwi[B_*H_*T_*K_];      // r * w_intra  (pre-scaled, per element)
__device__ float g_wkv[BH_*N_*K_*K_];     // per-chunk (k*w_inter)^T @ v
__device__ float g_states[BH_*N_*K_*K_];  // state BEFORE each chunk
__device__ float g_wse[BH_*N_*K_];        // exp(sum_t w_log) per chunk per k

// ---- phase1 shared memory layout (floats) ----
#define O_CUM   0        // 128x64 cumsum  (aliases O_A)
#define O_WL    8192     // 128x64 w_log   (aliases O_A upper half; dead after cumsum)
#define O_A     0        // 128x128 attention matrix (written after cum is dead)
#define O_RR    16384    // 128x64 r (transformed in place to r*r_dec)
#define O_KT    24576    // 64 x 132 : kk transposed, stride 132 (k * k_inv)
#define KT_STRIDE 132
#define O_V     33024    // 128x64 v
#define O_KR    41216    // 128x64 raw k
#define O_DIAG  49408    // 128
#define O_U     49536    // 64
#define O_EWO   49600    // 64 : exp(ws - off)
#define O_EO    49664    // 64 : exp(off)
#define SMEM1_FLOATS 49728
#define SMEM1_BYTES  (SMEM1_FLOATS * 4)

__global__ void __launch_bounds__(256, 1)
rwkv_phase1(const float* __restrict__ r, const float* __restrict__ k,
            const float* __restrict__ v, const float* __restrict__ w,
            const float* __restrict__ u, float* __restrict__ out)
{
    extern __shared__ float sm[];
    const int tid = threadIdx.x;
    const int bhn = blockIdx.x;
    const int bh  = bhn >> 4;
    const int n   = bhn & 15;
    const int h   = bh & (H_ - 1);
    const int base = bh * (T_ * K_) + n * (CH_ * K_);

    // ---- step 1: load r, k(raw), v, w_log into smem (float4, coalesced) ----
    {
        const float4* r4 = (const float4*)(r + base);
        const float4* k4 = (const float4*)(k + base);
        const float4* v4 = (const float4*)(v + base);
        const float4* w4 = (const float4*)(w + base);
        float4* srr = (float4*)(sm + O_RR);
        float4* skr = (float4*)(sm + O_KR);
        float4* sv  = (float4*)(sm + O_V);
        float4* swl = (float4*)(sm + O_WL);
        #pragma unroll
        for (int it = 0; it < 8; ++it) {
            int i = tid + it * 256;
            srr[i] = r4[i];
            skr[i] = k4[i];
            sv[i]  = v4[i];
            float4 ww = w4[i];
            ww.x = fmaxf(ww.x, LOGMIN);
            ww.y = fmaxf(ww.y, LOGMIN);
            ww.z = fmaxf(ww.z, LOGMIN);
            ww.w = fmaxf(ww.w, LOGMIN);
            swl[i] = ww;
        }
        if (tid < K_) sm[O_U + tid] = u[h * K_ + tid];
    }
    __syncthreads();

    // ---- step 2: cumsum per column (tid<64); diag (64<=tid<192) ----
    if (tid < 64) {
        float run = 0.f;
        #pragma unroll 8
        for (int t = 0; t < CH_; ++t) {
            run += sm[O_WL + t * 64 + tid];
            sm[O_CUM + t * 64 + tid] = run;
        }
        float off = sm[O_CUM + 63 * 64 + tid];
        sm[O_EWO + tid] = __expf(run - off);   // exp(ws - off)
        sm[O_EO + tid]  = __expf(off);         // exp(off)
        g_wse[(bh * N_ + n) * K_ + tid] = __expf(run);
    } else if (tid < 192) {
        int t = tid - 64;
        float d = 0.f;
        #pragma unroll 8
        for (int q = 0; q < 64; ++q) {
            int kk = (t + q) & 63;     // skew to avoid bank conflicts
            d += sm[O_RR + t * 64 + kk] * sm[O_U + kk] * sm[O_KR + t * 64 + kk];
        }
        sm[O_DIAG + t] = d;
    }
    __syncthreads();

    // ---- step 4: transform r -> r*r_dec (in place), k -> k*k_inv (transposed),
    //              and emit r*w_intra to global scratch ----
    #pragma unroll
    for (int it = 0; it < 32; ++it) {
        int idx = tid + it * 256;
        int t = idx >> 6, kk = idx & 63;
        float c   = sm[O_CUM + idx];
        float cp  = t ? sm[O_CUM + idx - 64] : 0.f;
        float off = sm[O_CUM + 63 * 64 + kk];
        float rr = sm[O_RR + idx] * __expf(cp - off);
        sm[O_RR + idx] = rr;
        g_rwi[base + idx] = rr * sm[O_EO + kk];                 // r * exp(cum_prev)
        sm[O_KT + kk * KT_STRIDE + t] = sm[O_KR + idx] * __expf(off - c);
    }
    __syncthreads();

    const int ty = tid >> 4;     // 0..15
    const int tx = tid & 15;     // 0..15

    // ---- step 5: a = rr @ kk^T (128x128, K=64), mask + diag, store to s_a ----
    {
        const int i0 = ty * 8, j0 = tx * 8;
        float acc[8][8];
        #pragma unroll
        for (int ii = 0; ii < 8; ++ii)
            #pragma unroll
            for (int jj = 0; jj < 8; ++jj) acc[ii][jj] = 0.f;

        #pragma unroll 4
        for (int kk = 0; kk < 64; ++kk) {
            float ra[8];
            #pragma unroll
            for (int ii = 0; ii < 8; ++ii) ra[ii] = sm[O_RR + (i0 + ii) * 64 + kk];
            float4 b0 = *(const float4*)&sm[O_KT + kk * KT_STRIDE + j0];
            float4 b1 = *(const float4*)&sm[O_KT + kk * KT_STRIDE + j0 + 4];
            float kb[8] = {b0.x, b0.y, b0.z, b0.w, b1.x, b1.y, b1.z, b1.w};
            #pragma unroll
            for (int ii = 0; ii < 8; ++ii)
                #pragma unroll
                for (int jj = 0; jj < 8; ++jj)
                    acc[ii][jj] = fmaf(ra[ii], kb[jj], acc[ii][jj]);
        }
        #pragma unroll
        for (int ii = 0; ii < 8; ++ii) {
            int row = i0 + ii;
            float dg = sm[O_DIAG + row];
            #pragma unroll
            for (int jj = 0; jj < 8; ++jj) {
                int col = j0 + jj;
                float val = (col < row) ? acc[ii][jj] : ((col == row) ? dg : 0.f);
                sm[O_A + row * 128 + col] = val;
            }
        }
    }
    __syncthreads();

    // ---- step 6: out_intra = a @ v  (128x64), store directly to d_out ----
    {
        const int i0 = ty * 8, j0 = tx * 4;
        float acc[8][4];
        #pragma unroll
        for (int ii = 0; ii < 8; ++ii)
            #pragma unroll
            for (int jj = 0; jj < 4; ++jj) acc[ii][jj] = 0.f;

        #pragma unroll 4
        for (int p = 0; p < 128; ++p) {
            float4 vv = *(const float4*)&sm[O_V + p * 64 + j0];
            #pragma unroll
            for (int ii = 0; ii < 8; ++ii) {
                float av = sm[O_A + (i0 + ii) * 128 + p];
                acc[ii][0] = fmaf(av, vv.x, acc[ii][0]);
                acc[ii][1] = fmaf(av, vv.y, acc[ii][1]);
                acc[ii][2] = fmaf(av, vv.z, acc[ii][2]);
                acc[ii][3] = fmaf(av, vv.w, acc[ii][3]);
            }
        }
        #pragma unroll
        for (int ii = 0; ii < 8; ++ii) {
            float4 o = {acc[ii][0], acc[ii][1], acc[ii][2], acc[ii][3]};
            *(float4*)&out[base + (i0 + ii) * 64 + j0] = o;
        }
    }

    // ---- step 7: wkv = (k*w_inter)^T @ v  (64x64) -> scratch ----
    {
        const int kd0 = ty * 4, vd0 = tx * 4;
        float acc[4][4];
        #pragma unroll
        for (int ii = 0; ii < 4; ++ii)
            #pragma unroll
            for (int jj = 0; jj < 4; ++jj) acc[ii][jj] = 0.f;

        #pragma unroll 4
        for (int t = 0; t < 128; ++t) {
            float4 vv = *(const float4*)&sm[O_V + t * 64 + vd0];
            #pragma unroll
            for (int ii = 0; ii < 4; ++ii) {
                float ka = sm[O_KT + (kd0 + ii) * KT_STRIDE + t];
                acc[ii][0] = fmaf(ka, vv.x, acc[ii][0]);
                acc[ii][1] = fmaf(ka, vv.y, acc[ii][1]);
                acc[ii][2] = fmaf(ka, vv.z, acc[ii][2]);
                acc[ii][3] = fmaf(ka, vv.w, acc[ii][3]);
            }
        }
        int wb = (bh * N_ + n) * (K_ * K_);
        #pragma unroll
        for (int ii = 0; ii < 4; ++ii) {
            float s = sm[O_EWO + kd0 + ii];   // exp(ws - off): kk held exp(off - cum)
            float4 o = {acc[ii][0] * s, acc[ii][1] * s, acc[ii][2] * s, acc[ii][3] * s};
            *(float4*)&g_wkv[wb + (kd0 + ii) * 64 + vd0] = o;
        }
    }
}

// ---- phase 2: sequential scan over chunks per (b,h) ----
__global__ void __launch_bounds__(256, 1)
rwkv_phase2(const float* __restrict__ state0, float* __restrict__ out_final)
{
    const int bh = blockIdx.x;
    const int tid = threadIdx.x;
    float s[16];
    const float* src = state0 + bh * (K_ * K_);
    #pragma unroll
    for (int i = 0; i < 16; ++i) s[i] = src[i * 256 + tid];

    for (int n = 0; n < N_; ++n) {
        const int ob = (bh * N_ + n) * (K_ * K_);
        const int wb = (bh * N_ + n) * K_;
        #pragma unroll
        for (int i = 0; i < 16; ++i) {
            int e = i * 256 + tid;
            g_states[ob + e] = s[i];
            float wse = __ldg(&g_wse[wb + (e >> 6)]);
            s[i] = fmaf(s[i], wse, g_wkv[ob + e]);
        }
    }
    #pragma unroll
    for (int i = 0; i < 16; ++i) out_final[bh * (K_ * K_) + i * 256 + tid] = s[i];
}

// ---- phase 3: out += (r*w_intra) @ states[chunk] ----
#define SMEM3_FLOATS (4096 + 8192)
#define SMEM3_BYTES  (SMEM3_FLOATS * 4)

__global__ void __launch_bounds__(256, 1)
rwkv_phase3(float* __restrict__ out)
{
    extern __shared__ float sm[];
    float* s_s  = sm;          // 64x64 state
    float* s_rw = sm + 4096;   // 128x64 r*w_intra
    const int tid = threadIdx.x;
    const int bhn = blockIdx.x;
    const int bh = bhn >> 4, n = bhn & 15;
    const int base = bh * (T_ * K_) + n * (CH_ * K_);
    const int sb = bhn * (K_ * K_);

    {
        const float4* st4 = (const float4*)(g_states + sb);
        const float4* rw4 = (const float4*)(g_rwi + base);
        #pragma unroll
        for (int it = 0; it < 4; ++it) ((float4*)s_s)[tid + it * 256] = st4[tid + it * 256];
        #pragma unroll
        for (int it = 0; it < 8; ++it) ((float4*)s_rw)[tid + it * 256] = rw4[tid + it * 256];
    }
    __syncthreads();

    const int ty = tid >> 4, tx = tid & 15;
    const int i0 = ty * 8, j0 = tx * 4;
    float acc[8][4];
    #pragma unroll
    for (int ii = 0; ii < 8; ++ii)
        #pragma unroll
        for (int jj = 0; jj < 4; ++jj) acc[ii][jj] = 0.f;

    #pragma unroll 4
    for (int kd = 0; kd < 64; ++kd) {
        float4 sv = *(const float4*)&s_s[kd * 64 + j0];
        #pragma unroll
        for (int ii = 0; ii < 8; ++ii) {
            float rv = s_rw[(i0 + ii) * 64 + kd];
            acc[ii][0] = fmaf(rv, sv.x, acc[ii][0]);
            acc[ii][1] = fmaf(rv, sv.y, acc[ii][1]);
            acc[ii][2] = fmaf(rv, sv.z, acc[ii][2]);
            acc[ii][3] = fmaf(rv, sv.w, acc[ii][3]);
        }
    }
    #pragma unroll
    for (int ii = 0; ii < 8; ++ii) {
        float4* p = (float4*)&out[base + (i0 + ii) * 64 + j0];
        float4 cur = *p;
        cur.x += acc[ii][0]; cur.y += acc[ii][1];
        cur.z += acc[ii][2]; cur.w += acc[ii][3];
        *p = cur;
    }
}

extern "C" void kernel_launch(void* const* d_in, const int* in_sizes, int n_in,
                              void* d_out, int out_size)
{
    (void)in_sizes; (void)n_in; (void)out_size;
    const float* r  = (const float*)d_in[0];
    const float* k  = (const float*)d_in[1];
    const float* v  = (const float*)d_in[2];
    const float* w  = (const float*)d_in[3];
    const float* u  = (const float*)d_in[4];
    const float* s0 = (const float*)d_in[5];
    float* out  = (float*)d_out;
    float* outF = out + OUT_ELEMS;

    cudaFuncSetAttribute(rwkv_phase1, cudaFuncAttributeMaxDynamicSharedMemorySize, SMEM1_BYTES);
    cudaFuncSetAttribute(rwkv_phase3, cudaFuncAttributeMaxDynamicSharedMemorySize, SMEM3_BYTES);

    rwkv_phase1<<<BH_ * N_, 256, SMEM1_BYTES>>>(r, k, v, w, u, out);
    rwkv_phase2<<<BH_, 256>>>(s0, outF);
    rwkv_phase3<<<BH_ * N_, 256, SMEM3_BYTES>>>(out);
}

// round 3
// speedup vs baseline: 1.4348x; 1.4348x over previous
#include <cuda_runtime.h>
#include <cstdint>

#define B_ 4
#define H_ 16
#define T_ 2048
#define K_ 64
#define CH_ 128
#define N_ 16
#define BH_ (B_*H_)
#define OUT_ELEMS (B_*H_*T_*K_)
#define LOGMIN (-5.2983174324035645f)

// ---- scratch ----
__device__ float g_rwi[B_*H_*T_*K_];      // r * exp(cum_prev)  (tf32-rounded)
__device__ float g_wkv[BH_*N_*K_*K_];
__device__ float g_states[BH_*N_*K_*K_];
__device__ float g_wse[BH_*N_*K_];

// ---- phase1 smem layout (float offsets) ----
#define O_RR    0        // 128 x 64, stride 68  (8704)
#define O_KK    8704     // 128 x 64, stride 68  (8704)
#define O_A     0        // 128 x 128, stride 132 (16896) -- aliases RR+KK after MMA1
#define O_V     17408    // 128 x 64, stride 72  (9216)
#define O_KW    26624    // 128 x 64, stride 72  (9216)  [t][kdim], w_inter baked in
#define O_CUM   35840    // 128 x 64, stride 64  (8192)
#define O_U     44032
#define O_DIAG  44096
#define O_EMOFF 44224
#define O_EOFF  44288
#define O_EWS   44352
#define O_SEG   44416    // 4 x 64
#define SMEM1_FLOATS 44672
#define SMEM1_BYTES  (SMEM1_FLOATS*4)

__device__ __forceinline__ float f2tf(float x) {
    uint32_t r;
    asm("cvt.rna.tf32.f32 %0, %1;" : "=r"(r) : "f"(x));
    return __uint_as_float(r);
}
__device__ __forceinline__ void mma1688(float* c, uint32_t a0, uint32_t a1, uint32_t a2, uint32_t a3,
                                        uint32_t b0, uint32_t b1) {
    asm volatile("mma.sync.aligned.m16n8k8.row.col.f32.tf32.tf32.f32 "
                 "{%0,%1,%2,%3},{%4,%5,%6,%7},{%8,%9},{%0,%1,%2,%3};"
                 : "+f"(c[0]), "+f"(c[1]), "+f"(c[2]), "+f"(c[3])
                 : "r"(a0), "r"(a1), "r"(a2), "r"(a3), "r"(b0), "r"(b1));
}
#define FB(x) __float_as_uint(x)

__global__ void __launch_bounds__(256)
rwkv_phase1(const float* __restrict__ r, const float* __restrict__ k,
            const float* __restrict__ v, const float* __restrict__ w,
            const float* __restrict__ u, float* __restrict__ out)
{
    extern __shared__ float sm[];
    const int tid = threadIdx.x;
    const int wid = tid >> 5, lid = tid & 31;
    const int ly = lid >> 2, lx = lid & 3;
    const int bhn = blockIdx.x;
    const int bh = bhn >> 4, n = bhn & 15;
    const int h = bh & (H_ - 1);
    const int base = bh * (T_ * K_) + n * (CH_ * K_);

    // ---- pass A: w -> cum region; v -> s_v (tf32, stride 72); u ----
    {
        const float4* w4 = (const float4*)(w + base);
        const float4* v4 = (const float4*)(v + base);
        #pragma unroll
        for (int it = 0; it < 8; ++it) {
            int f4 = tid + it * 256;
            int t = f4 >> 4, k0 = (f4 & 15) * 4;
            float4 ww = w4[f4];
            ww.x = fmaxf(ww.x, LOGMIN); ww.y = fmaxf(ww.y, LOGMIN);
            ww.z = fmaxf(ww.z, LOGMIN); ww.w = fmaxf(ww.w, LOGMIN);
            *(float4*)&sm[O_CUM + t * 64 + k0] = ww;
            float4 vv = v4[f4];
            vv.x = f2tf(vv.x); vv.y = f2tf(vv.y); vv.z = f2tf(vv.z); vv.w = f2tf(vv.w);
            *(float4*)&sm[O_V + t * 72 + k0] = vv;
        }
        if (tid < 64) sm[O_U + tid] = u[h * 64 + tid];
    }
    __syncthreads();

    // ---- pass B: segmented cumsum over t, per k-column ----
    {
        int kq = tid & 63, seg = tid >> 6;
        float run = 0.f;
        #pragma unroll
        for (int tt = 0; tt < 32; ++tt) {
            int idx = (seg * 32 + tt) * 64 + kq;
            run += sm[O_CUM + idx];
            sm[O_CUM + idx] = run;
        }
        sm[O_SEG + seg * 64 + kq] = run;
    }
    __syncthreads();
    {
        int kq = tid & 63, seg = tid >> 6;
        if (seg > 0) {
            float pre = sm[O_SEG + kq];
            if (seg > 1) pre += sm[O_SEG + 64 + kq];
            if (seg > 2) pre += sm[O_SEG + 128 + kq];
            #pragma unroll
            for (int tt = 0; tt < 32; ++tt) sm[O_CUM + (seg * 32 + tt) * 64 + kq] += pre;
        }
    }
    __syncthreads();
    if (tid < 64) {
        float off = sm[O_CUM + 63 * 64 + tid];
        float ws  = sm[O_CUM + 127 * 64 + tid];
        float ews = __expf(ws);
        sm[O_EMOFF + tid] = __expf(-off);
        sm[O_EOFF  + tid] = __expf(off);
        sm[O_EWS   + tid] = ews;
        g_wse[(bh * N_ + n) * K_ + tid] = ews;
    }
    __syncthreads();

    // ---- pass C: rr, kk (stride 68), kw (stride 72), g_rwi, diag ----
    {
        const float4* r4g = (const float4*)(r + base);
        const float4* k4g = (const float4*)(k + base);
        #pragma unroll
        for (int it = 0; it < 8; ++it) {
            int f4 = tid + it * 256;
            int t = f4 >> 4, k0 = (f4 & 15) * 4;
            float4 rv = r4g[f4];
            float4 kv = k4g[f4];
            float4 c4 = *(const float4*)&sm[O_CUM + t * 64 + k0];
            float4 cp4 = (t > 0) ? *(const float4*)&sm[O_CUM + (t - 1) * 64 + k0]
                                 : make_float4(0.f, 0.f, 0.f, 0.f);
            float4 emo = *(const float4*)&sm[O_EMOFF + k0];
            float4 eof = *(const float4*)&sm[O_EOFF + k0];
            float4 ews = *(const float4*)&sm[O_EWS + k0];
            float4 uu  = *(const float4*)&sm[O_U + k0];
            float re[4] = {rv.x, rv.y, rv.z, rv.w};
            float ke[4] = {kv.x, kv.y, kv.z, kv.w};
            float ce[4] = {c4.x, c4.y, c4.z, c4.w};
            float cpe[4] = {cp4.x, cp4.y, cp4.z, cp4.w};
            float emoe[4] = {emo.x, emo.y, emo.z, emo.w};
            float eofe[4] = {eof.x, eof.y, eof.z, eof.w};
            float ewse[4] = {ews.x, ews.y, ews.z, ews.w};
            float ue[4] = {uu.x, uu.y, uu.z, uu.w};
            float rrv[4], kkv[4], kwv[4], rwv[4];
            float dpart = 0.f;
            #pragma unroll
            for (int e = 0; e < 4; ++e) {
                float ecp = __expf(cpe[e]);
                float emc = __expf(-ce[e]);
                rwv[e] = f2tf(re[e] * ecp);                  // r * exp(cum_prev)
                rrv[e] = f2tf(re[e] * ecp * emoe[e]);        // r * exp(cp - off)
                kkv[e] = f2tf(ke[e] * eofe[e] * emc);        // k * exp(off - cum)
                kwv[e] = f2tf(ke[e] * ewse[e] * emc);        // k * exp(ws - cum)
                dpart += re[e] * ue[e] * ke[e];
            }
            *(float4*)&sm[O_RR + t * 68 + k0] = make_float4(rrv[0], rrv[1], rrv[2], rrv[3]);
            *(float4*)&sm[O_KK + t * 68 + k0] = make_float4(kkv[0], kkv[1], kkv[2], kkv[3]);
            *(float4*)&sm[O_KW + t * 72 + k0] = make_float4(kwv[0], kwv[1], kwv[2], kwv[3]);
            *(float4*)&g_rwi[base + f4 * 4]   = make_float4(rwv[0], rwv[1], rwv[2], rwv[3]);
            float dv = dpart;
            #pragma unroll
            for (int s = 1; s < 16; s <<= 1) dv += __shfl_xor_sync(0xffffffffu, dv, s, 16);
            if ((tid & 15) == 0) sm[O_DIAG + t] = dv;
        }
    }
    __syncthreads();

    // ---- MMA1: a[128x128] = rr @ kk^T (tf32 tensor cores) ----
    const int i0 = wid * 16;
    float c1[16][4];
    #pragma unroll
    for (int nt = 0; nt < 16; ++nt)
        #pragma unroll
        for (int e = 0; e < 4; ++e) c1[nt][e] = 0.f;

    #pragma unroll
    for (int ks = 0; ks < 8; ++ks) {
        int k0 = ks * 8;
        const float* ar = &sm[O_RR + (i0 + ly) * 68 + k0 + lx];
        uint32_t a0 = FB(ar[0]), a1 = FB(ar[8 * 68]), a2 = FB(ar[4]), a3 = FB(ar[8 * 68 + 4]);
        #pragma unroll
        for (int nt = 0; nt < 16; ++nt) {
            const float* br = &sm[O_KK + (nt * 8 + ly) * 68 + k0 + lx];
            mma1688(c1[nt], a0, a1, a2, a3, FB(br[0]), FB(br[4]));
        }
    }
    __syncthreads();   // all MMA1 reads of rr/kk done before s_a overwrites them

    // ---- epilogue 1: tril(-1) mask + diag, tf32-round, store a (stride 132) ----
    {
        int il = i0 + ly, ih = il + 8;
        float dgl = f2tf(sm[O_DIAG + il]);
        float dgh = f2tf(sm[O_DIAG + ih]);
        #pragma unroll
        for (int nt = 0; nt < 16; ++nt) {
            int jb = nt * 8 + 2 * lx;
            float v0 = (jb     < il) ? f2tf(c1[nt][0]) : ((jb     == il) ? dgl : 0.f);
            float v1 = (jb + 1 < il) ? f2tf(c1[nt][1]) : ((jb + 1 == il) ? dgl : 0.f);
            float v2 = (jb     < ih) ? f2tf(c1[nt][2]) : ((jb     == ih) ? dgh : 0.f);
            float v3 = (jb + 1 < ih) ? f2tf(c1[nt][3]) : ((jb + 1 == ih) ? dgh : 0.f);
            *(float2*)&sm[O_A + il * 132 + jb] = make_float2(v0, v1);
            *(float2*)&sm[O_A + ih * 132 + jb] = make_float2(v2, v3);
        }
    }
    __syncthreads();

    // ---- MMA2: out[128x64] = a @ v ----
    {
        float c2[8][4];
        #pragma unroll
        for (int nt = 0; nt < 8; ++nt)
            #pragma unroll
            for (int e = 0; e < 4; ++e) c2[nt][e] = 0.f;
        #pragma unroll
        for (int ks = 0; ks < 16; ++ks) {
            int k0 = ks * 8;
            const float* ar = &sm[O_A + (i0 + ly) * 132 + k0 + lx];
            uint32_t a0 = FB(ar[0]), a1 = FB(ar[8 * 132]), a2 = FB(ar[4]), a3 = FB(ar[8 * 132 + 4]);
            #pragma unroll
            for (int nt = 0; nt < 8; ++nt) {
                const float* br = &sm[O_V + (k0 + lx) * 72 + nt * 8 + ly];
                mma1688(c2[nt], a0, a1, a2, a3, FB(br[0]), FB(br[4 * 72]));
            }
        }
        int il = i0 + ly, ih = il + 8;
        #pragma unroll
        for (int nt = 0; nt < 8; ++nt) {
            int jb = nt * 8 + 2 * lx;
            *(float2*)&out[base + il * 64 + jb] = make_float2(c2[nt][0], c2[nt][1]);
            *(float2*)&out[base + ih * 64 + jb] = make_float2(c2[nt][2], c2[nt][3]);
        }
    }

    // ---- MMA3: wkv[64x64] = kw^T @ v ----
    {
        const int i0k = (wid & 3) * 16, j0c = (wid >> 2) * 32;
        float c3[4][4];
        #pragma unroll
        for (int nt = 0; nt < 4; ++nt)
            #pragma unroll
            for (int e = 0; e < 4; ++e) c3[nt][e] = 0.f;
        #pragma unroll
        for (int ks = 0; ks < 16; ++ks) {
            int k0 = ks * 8;
            const float* ac = &sm[O_KW + (k0 + lx) * 72 + i0k + ly];
            uint32_t a0 = FB(ac[0]), a1 = FB(ac[8]), a2 = FB(ac[4 * 72]), a3 = FB(ac[4 * 72 + 8]);
            #pragma unroll
            for (int nt = 0; nt < 4; ++nt) {
                const float* br = &sm[O_V + (k0 + lx) * 72 + j0c + nt * 8 + ly];
                mma1688(c3[nt], a0, a1, a2, a3, FB(br[0]), FB(br[4 * 72]));
            }
        }
        int wb = bhn * (K_ * K_);
        int il = i0k + ly, ih = il + 8;
        #pragma unroll
        for (int nt = 0; nt < 4; ++nt) {
            int jb = j0c + nt * 8 + 2 * lx;
            *(float2*)&g_wkv[wb + il * 64 + jb] = make_float2(c3[nt][0], c3[nt][1]);
            *(float2*)&g_wkv[wb + ih * 64 + jb] = make_float2(c3[nt][2], c3[nt][3]);
        }
    }
}

// ---- phase 2: sequential scan over chunks per (b,h) ----
__global__ void __launch_bounds__(256, 1)
rwkv_phase2(const float* __restrict__ state0, float* __restrict__ out_final)
{
    const int bh = blockIdx.x;
    const int tid = threadIdx.x;
    float s[16];
    const float* src = state0 + bh * (K_ * K_);
    #pragma unroll
    for (int i = 0; i < 16; ++i) s[i] = src[i * 256 + tid];

    for (int n = 0; n < N_; ++n) {
        const int ob = (bh * N_ + n) * (K_ * K_);
        const int wb = (bh * N_ + n) * K_;
        #pragma unroll
        for (int i = 0; i < 16; ++i) {
            int e = i * 256 + tid;
            g_states[ob + e] = s[i];
            float wse = __ldg(&g_wse[wb + (e >> 6)]);
            s[i] = fmaf(s[i], wse, g_wkv[ob + e]);
        }
    }
    #pragma unroll
    for (int i = 0; i < 16; ++i) out_final[bh * (K_ * K_) + i * 256 + tid] = s[i];
}

// ---- phase 3: out += (r*w_intra) @ states[chunk], tf32 mma ----
#define P3_ST  0          // 64 x 64, stride 72 (4608)
#define P3_RW  4608       // 128 x 64, stride 68 (8704)
#define SMEM3_FLOATS 13312
#define SMEM3_BYTES  (SMEM3_FLOATS * 4)

__global__ void __launch_bounds__(256)
rwkv_phase3(float* __restrict__ out)
{
    extern __shared__ float sm[];
    const int tid = threadIdx.x;
    const int wid = tid >> 5, lid = tid & 31;
    const int ly = lid >> 2, lx = lid & 3;
    const int bhn = blockIdx.x;
    const int bh = bhn >> 4, n = bhn & 15;
    const int base = bh * (T_ * K_) + n * (CH_ * K_);
    const int sb = bhn * (K_ * K_);

    {
        const float4* st4 = (const float4*)(g_states + sb);
        #pragma unroll
        for (int it = 0; it < 4; ++it) {
            int f4 = tid + it * 256;
            int kd = f4 >> 4, j0 = (f4 & 15) * 4;
            float4 sv = st4[f4];
            sv.x = f2tf(sv.x); sv.y = f2tf(sv.y); sv.z = f2tf(sv.z); sv.w = f2tf(sv.w);
            *(float4*)&sm[P3_ST + kd * 72 + j0] = sv;
        }
        const float4* rw4 = (const float4*)(g_rwi + base);
        #pragma unroll
        for (int it = 0; it < 8; ++it) {
            int f4 = tid + it * 256;
            int t = f4 >> 4, k0 = (f4 & 15) * 4;
            *(float4*)&sm[P3_RW + t * 68 + k0] = rw4[f4];   // already tf32-rounded
        }
    }
    __syncthreads();

    const int i0 = wid * 16;
    float c[8][4];
    #pragma unroll
    for (int nt = 0; nt < 8; ++nt)
        #pragma unroll
        for (int e = 0; e < 4; ++e) c[nt][e] = 0.f;

    #pragma unroll
    for (int ks = 0; ks < 8; ++ks) {
        int k0 = ks * 8;
        const float* ar = &sm[P3_RW + (i0 + ly) * 68 + k0 + lx];
        uint32_t a0 = FB(ar[0]), a1 = FB(ar[8 * 68]), a2 = FB(ar[4]), a3 = FB(ar[8 * 68 + 4]);
        #pragma unroll
        for (int nt = 0; nt < 8; ++nt) {
            const float* br = &sm[P3_ST + (k0 + lx) * 72 + nt * 8 + ly];
            mma1688(c[nt], a0, a1, a2, a3, FB(br[0]), FB(br[4 * 72]));
        }
    }

    int il = i0 + ly, ih = il + 8;
    #pragma unroll
    for (int nt = 0; nt < 8; ++nt) {
        int jb = nt * 8 + 2 * lx;
        float2* pl = (float2*)&out[base + il * 64 + jb];
        float2* ph = (float2*)&out[base + ih * 64 + jb];
        float2 cl = *pl, chh = *ph;
        cl.x += c[nt][0]; cl.y += c[nt][1];
        chh.x += c[nt][2]; chh.y += c[nt][3];
        *pl = cl; *ph = chh;
    }
}

extern "C" void kernel_launch(void* const* d_in, const int* in_sizes, int n_in,
                              void* d_out, int out_size)
{
    (void)in_sizes; (void)n_in; (void)out_size;
    const float* r  = (const float*)d_in[0];
    const float* k  = (const float*)d_in[1];
    const float* v  = (const float*)d_in[2];
    const float* w  = (const float*)d_in[3];
    const float* u  = (const float*)d_in[4];
    const float* s0 = (const float*)d_in[5];
    float* out  = (float*)d_out;
    float* outF = out + OUT_ELEMS;

    cudaFuncSetAttribute(rwkv_phase1, cudaFuncAttributeMaxDynamicSharedMemorySize, SMEM1_BYTES);
    cudaFuncSetAttribute(rwkv_phase3, cudaFuncAttributeMaxDynamicSharedMemorySize, SMEM3_BYTES);

    rwkv_phase1<<<BH_ * N_, 256, SMEM1_BYTES>>>(r, k, v, w, u, out);
    rwkv_phase2<<<BH_, 256>>>(s0, outF);
    rwkv_phase3<<<BH_ * N_, 256, SMEM3_BYTES>>>(out);
}

// round 4
// speedup vs baseline: 1.6503x; 1.1502x over previous
#include <cuda_runtime.h>
#include <cstdint>

#define B_ 4
#define H_ 16
#define T_ 2048
#define K_ 64
#define CH_ 128
#define N_ 16
#define BH_ (B_*H_)
#define OUT_ELEMS (B_*H_*T_*K_)
#define LOGMIN (-5.2983174324035645f)

// ---- scratch ----
__device__ float g_rwi[B_*H_*T_*K_];      // r * exp(cum_prev)  (tf32-rounded)
__device__ float g_wkv[BH_*N_*K_*K_];
__device__ float g_states[BH_*N_*K_*K_];
__device__ float g_wse[BH_*N_*K_];

// ---- phase1 smem layout (float offsets) ----
#define O_RW    0        // 128 x 64, stride 68  (8704)   A-operand of MMA1 (= r*exp(cp))
#define O_CUM   8704     // 128 x 64, stride 64  (8192)
#define O_A     0        // 128 x 128, stride 132 (16896) -- aliases RW+CUM after MMA1
#define O_KK    16896    // 128 x 64, stride 76  (9728)   k*exp(-cum); MMA1-B and MMA3-A
#define O_V     26624    // 128 x 64, stride 72  (9216)
#define O_U     35840
#define O_DIAG  35904    // 128
#define O_EWS   36032    // 64
#define O_SEG   36096    // 8 x 64
#define SMEM1_FLOATS 36608
#define SMEM1_BYTES  (SMEM1_FLOATS*4)

__device__ __forceinline__ float f2tf(float x) {
    uint32_t r;
    asm("cvt.rna.tf32.f32 %0, %1;" : "=r"(r) : "f"(x));
    return __uint_as_float(r);
}
__device__ __forceinline__ void mma1688(float* c, uint32_t a0, uint32_t a1, uint32_t a2, uint32_t a3,
                                        uint32_t b0, uint32_t b1) {
    asm volatile("mma.sync.aligned.m16n8k8.row.col.f32.tf32.tf32.f32 "
                 "{%0,%1,%2,%3},{%4,%5,%6,%7},{%8,%9},{%0,%1,%2,%3};"
                 : "+f"(c[0]), "+f"(c[1]), "+f"(c[2]), "+f"(c[3])
                 : "r"(a0), "r"(a1), "r"(a2), "r"(a3), "r"(b0), "r"(b1));
}
#define FB(x) __float_as_uint(x)

__global__ void __launch_bounds__(512)
rwkv_phase1(const float* __restrict__ r, const float* __restrict__ k,
            const float* __restrict__ v, const float* __restrict__ w,
            const float* __restrict__ u, float* __restrict__ out)
{
    extern __shared__ float sm[];
    const int tid = threadIdx.x;
    const int wid = tid >> 5, lid = tid & 31;
    const int ly = lid >> 2, lx = lid & 3;
    const int bhn = blockIdx.x;
    const int bh = bhn >> 4, n = bhn & 15;
    const int h = bh & (H_ - 1);
    const int base = bh * (T_ * K_) + n * (CH_ * K_);

    // ---- pass A: w -> CUM (pre-clipped); v -> V (tf32, stride 72); u ----
    {
        const float4* w4 = (const float4*)(w + base);
        const float4* v4 = (const float4*)(v + base);
        #pragma unroll
        for (int it = 0; it < 4; ++it) {
            int f4 = tid + it * 512;
            int t = f4 >> 4, k0 = (f4 & 15) * 4;
            float4 ww = w4[f4];
            ww.x = fmaxf(ww.x, LOGMIN); ww.y = fmaxf(ww.y, LOGMIN);
            ww.z = fmaxf(ww.z, LOGMIN); ww.w = fmaxf(ww.w, LOGMIN);
            *(float4*)&sm[O_CUM + t * 64 + k0] = ww;
            float4 vv = v4[f4];
            vv.x = f2tf(vv.x); vv.y = f2tf(vv.y); vv.z = f2tf(vv.z); vv.w = f2tf(vv.w);
            *(float4*)&sm[O_V + t * 72 + k0] = vv;
        }
        if (tid < 64) sm[O_U + tid] = u[h * 64 + tid];
    }
    __syncthreads();

    // ---- pass B: segmented cumsum (8 segments x 16 t-rows) ----
    {
        int kq = tid & 63, seg = tid >> 6;
        float run = 0.f;
        #pragma unroll
        for (int tt = 0; tt < 16; ++tt) {
            int idx = (seg * 16 + tt) * 64 + kq;
            run += sm[O_CUM + idx];
            sm[O_CUM + idx] = run;
        }
        sm[O_SEG + seg * 64 + kq] = run;
    }
    __syncthreads();
    {
        int kq = tid & 63, seg = tid >> 6;
        if (seg > 0) {
            float pre = 0.f;
            #pragma unroll
            for (int s = 0; s < 7; ++s)
                if (s < seg) pre += sm[O_SEG + s * 64 + kq];
            #pragma unroll
            for (int tt = 0; tt < 16; ++tt) sm[O_CUM + (seg * 16 + tt) * 64 + kq] += pre;
        }
    }
    __syncthreads();
    if (tid < 64) {
        float ws = sm[O_CUM + 127 * 64 + tid];
        float ews = __expf(ws);
        sm[O_EWS + tid] = ews;
        g_wse[(bh * N_ + n) * K_ + tid] = ews;
    }
    __syncthreads();

    // ---- pass C: rw (stride 68), kk (stride 76), g_rwi, diag ----
    {
        const float4* r4g = (const float4*)(r + base);
        const float4* k4g = (const float4*)(k + base);
        #pragma unroll
        for (int it = 0; it < 4; ++it) {
            int f4 = tid + it * 512;
            int t = f4 >> 4, k0 = (f4 & 15) * 4;
            float4 rv = r4g[f4];
            float4 kv = k4g[f4];
            float4 c4 = *(const float4*)&sm[O_CUM + t * 64 + k0];
            float4 cp4 = (t > 0) ? *(const float4*)&sm[O_CUM + (t - 1) * 64 + k0]
                                 : make_float4(0.f, 0.f, 0.f, 0.f);
            float4 uu = *(const float4*)&sm[O_U + k0];
            float re[4] = {rv.x, rv.y, rv.z, rv.w};
            float ke[4] = {kv.x, kv.y, kv.z, kv.w};
            float ce[4] = {c4.x, c4.y, c4.z, c4.w};
            float cpe[4] = {cp4.x, cp4.y, cp4.z, cp4.w};
            float ue[4] = {uu.x, uu.y, uu.z, uu.w};
            float rwv[4], kkv[4];
            float dpart = 0.f;
            #pragma unroll
            for (int e = 0; e < 4; ++e) {
                rwv[e] = f2tf(re[e] * __expf(cpe[e]));   // r * exp(cum_prev)
                kkv[e] = f2tf(ke[e] * __expf(-ce[e]));   // k * exp(-cum)
                dpart += re[e] * ue[e] * ke[e];
            }
            *(float4*)&sm[O_RW + t * 68 + k0] = make_float4(rwv[0], rwv[1], rwv[2], rwv[3]);
            *(float4*)&sm[O_KK + t * 76 + k0] = make_float4(kkv[0], kkv[1], kkv[2], kkv[3]);
            *(float4*)&g_rwi[base + f4 * 4]   = make_float4(rwv[0], rwv[1], rwv[2], rwv[3]);
            float dv = dpart;
            #pragma unroll
            for (int s = 1; s < 16; s <<= 1) dv += __shfl_xor_sync(0xffffffffu, dv, s, 16);
            if ((tid & 15) == 0) sm[O_DIAG + t] = dv;
        }
    }
    __syncthreads();

    // ---- MMA1: a[128x128] = rw @ kk^T   (warp: 16 rows x 64 cols) ----
    const int i0 = (wid & 7) * 16;
    const int jh = wid >> 3;              // 0..1 column half
    float c1[8][4];
    #pragma unroll
    for (int nt = 0; nt < 8; ++nt)
        #pragma unroll
        for (int e = 0; e < 4; ++e) c1[nt][e] = 0.f;

    #pragma unroll
    for (int ks = 0; ks < 8; ++ks) {
        int k0 = ks * 8;
        const float* ar = &sm[O_RW + (i0 + ly) * 68 + k0 + lx];
        uint32_t a0 = FB(ar[0]), a1 = FB(ar[8 * 68]), a2 = FB(ar[4]), a3 = FB(ar[8 * 68 + 4]);
        #pragma unroll
        for (int nt = 0; nt < 8; ++nt) {
            const float* br = &sm[O_KK + (jh * 64 + nt * 8 + ly) * 76 + k0 + lx];
            mma1688(c1[nt], a0, a1, a2, a3, FB(br[0]), FB(br[4]));
        }
    }

    // ---- MMA3: wkv[64x64] = kk^T @ v, scaled by ews[row]  (warp: 16x16 tile) ----
    {
        const int i0k = (wid & 3) * 16, j0c = (wid >> 2) * 16;
        float c3[2][4];
        #pragma unroll
        for (int nt = 0; nt < 2; ++nt)
            #pragma unroll
            for (int e = 0; e < 4; ++e) c3[nt][e] = 0.f;
        #pragma unroll
        for (int ks = 0; ks < 16; ++ks) {
            int k0 = ks * 8;
            const float* ac = &sm[O_KK + (k0 + lx) * 76 + i0k + ly];
            uint32_t a0 = FB(ac[0]), a1 = FB(ac[8]), a2 = FB(ac[4 * 76]), a3 = FB(ac[4 * 76 + 8]);
            #pragma unroll
            for (int nt = 0; nt < 2; ++nt) {
                const float* br = &sm[O_V + (k0 + lx) * 72 + j0c + nt * 8 + ly];
                mma1688(c3[nt], a0, a1, a2, a3, FB(br[0]), FB(br[4 * 72]));
            }
        }
        int wb = bhn * (K_ * K_);
        int il = i0k + ly, ih = il + 8;
        float sl = sm[O_EWS + il], sh = sm[O_EWS + ih];
        #pragma unroll
        for (int nt = 0; nt < 2; ++nt) {
            int jb = j0c + nt * 8 + 2 * lx;
            *(float2*)&g_wkv[wb + il * 64 + jb] = make_float2(c3[nt][0] * sl, c3[nt][1] * sl);
            *(float2*)&g_wkv[wb + ih * 64 + jb] = make_float2(c3[nt][2] * sh, c3[nt][3] * sh);
        }
    }
    __syncthreads();   // MMA1/MMA3 reads of RW done before A overwrites

    // ---- epilogue 1: tril(-1) mask + diag, tf32-round, store a (stride 132) ----
    {
        int il = i0 + ly, ih = il + 8;
        float dgl = f2tf(sm[O_DIAG + il]);
        float dgh = f2tf(sm[O_DIAG + ih]);
        #pragma unroll
        for (int nt = 0; nt < 8; ++nt) {
            int jb = jh * 64 + nt * 8 + 2 * lx;
            float v0 = (jb     < il) ? f2tf(c1[nt][0]) : ((jb     == il) ? dgl : 0.f);
            float v1 = (jb + 1 < il) ? f2tf(c1[nt][1]) : ((jb + 1 == il) ? dgl : 0.f);
            float v2 = (jb     < ih) ? f2tf(c1[nt][2]) : ((jb     == ih) ? dgh : 0.f);
            float v3 = (jb + 1 < ih) ? f2tf(c1[nt][3]) : ((jb + 1 == ih) ? dgh : 0.f);
            *(float2*)&sm[O_A + il * 132 + jb] = make_float2(v0, v1);
            *(float2*)&sm[O_A + ih * 132 + jb] = make_float2(v2, v3);
        }
    }
    __syncthreads();

    // ---- MMA2: out[128x64] = a @ v   (warp: 16 rows x 32 cols) ----
    {
        float c2[4][4];
        #pragma unroll
        for (int nt = 0; nt < 4; ++nt)
            #pragma unroll
            for (int e = 0; e < 4; ++e) c2[nt][e] = 0.f;
        #pragma unroll
        for (int ks = 0; ks < 16; ++ks) {
            int k0 = ks * 8;
            const float* ar = &sm[O_A + (i0 + ly) * 132 + k0 + lx];
            uint32_t a0 = FB(ar[0]), a1 = FB(ar[8 * 132]), a2 = FB(ar[4]), a3 = FB(ar[8 * 132 + 4]);
            #pragma unroll
            for (int nt = 0; nt < 4; ++nt) {
                const float* br = &sm[O_V + (k0 + lx) * 72 + jh * 32 + nt * 8 + ly];
                mma1688(c2[nt], a0, a1, a2, a3, FB(br[0]), FB(br[4 * 72]));
            }
        }
        int il = i0 + ly, ih = il + 8;
        #pragma unroll
        for (int nt = 0; nt < 4; ++nt) {
            int jb = jh * 32 + nt * 8 + 2 * lx;
            *(float2*)&out[base + il * 64 + jb] = make_float2(c2[nt][0], c2[nt][1]);
            *(float2*)&out[base + ih * 64 + jb] = make_float2(c2[nt][2], c2[nt][3]);
        }
    }
}

// ---- phase 2: sequential scan over chunks per (b,h) ----
__global__ void __launch_bounds__(256, 1)
rwkv_phase2(const float* __restrict__ state0, float* __restrict__ out_final)
{
    const int bh = blockIdx.x;
    const int tid = threadIdx.x;
    float s[16];
    const float* src = state0 + bh * (K_ * K_);
    #pragma unroll
    for (int i = 0; i < 16; ++i) s[i] = src[i * 256 + tid];

    for (int n = 0; n < N_; ++n) {
        const int ob = (bh * N_ + n) * (K_ * K_);
        const int wb = (bh * N_ + n) * K_;
        #pragma unroll
        for (int i = 0; i < 16; ++i) {
            int e = i * 256 + tid;
            g_states[ob + e] = s[i];
            float wse = __ldg(&g_wse[wb + (e >> 6)]);
            s[i] = fmaf(s[i], wse, g_wkv[ob + e]);
        }
    }
    #pragma unroll
    for (int i = 0; i < 16; ++i) out_final[bh * (K_ * K_) + i * 256 + tid] = s[i];
}

// ---- phase 3: out += (r*w_intra) @ states[chunk], tf32 mma, 512 threads ----
#define P3_ST  0          // 64 x 64, stride 72 (4608)
#define P3_RW  4608       // 128 x 64, stride 68 (8704)
#define SMEM3_FLOATS 13312
#define SMEM3_BYTES  (SMEM3_FLOATS * 4)

__global__ void __launch_bounds__(512)
rwkv_phase3(float* __restrict__ out)
{
    extern __shared__ float sm[];
    const int tid = threadIdx.x;
    const int wid = tid >> 5, lid = tid & 31;
    const int ly = lid >> 2, lx = lid & 3;
    const int bhn = blockIdx.x;
    const int bh = bhn >> 4, n = bhn & 15;
    const int base = bh * (T_ * K_) + n * (CH_ * K_);
    const int sb = bhn * (K_ * K_);

    {
        const float4* st4 = (const float4*)(g_states + sb);
        #pragma unroll
        for (int it = 0; it < 2; ++it) {
            int f4 = tid + it * 512;
            int kd = f4 >> 4, j0 = (f4 & 15) * 4;
            float4 sv = st4[f4];
            sv.x = f2tf(sv.x); sv.y = f2tf(sv.y); sv.z = f2tf(sv.z); sv.w = f2tf(sv.w);
            *(float4*)&sm[P3_ST + kd * 72 + j0] = sv;
        }
        const float4* rw4 = (const float4*)(g_rwi + base);
        #pragma unroll
        for (int it = 0; it < 4; ++it) {
            int f4 = tid + it * 512;
            int t = f4 >> 4, k0 = (f4 & 15) * 4;
            *(float4*)&sm[P3_RW + t * 68 + k0] = rw4[f4];   // already tf32-rounded
        }
    }
    __syncthreads();

    const int i0 = (wid & 7) * 16;
    const int jh = wid >> 3;
    float c[4][4];
    #pragma unroll
    for (int nt = 0; nt < 4; ++nt)
        #pragma unroll
        for (int e = 0; e < 4; ++e) c[nt][e] = 0.f;

    #pragma unroll
    for (int ks = 0; ks < 8; ++ks) {
        int k0 = ks * 8;
        const float* ar = &sm[P3_RW + (i0 + ly) * 68 + k0 + lx];
        uint32_t a0 = FB(ar[0]), a1 = FB(ar[8 * 68]), a2 = FB(ar[4]), a3 = FB(ar[8 * 68 + 4]);
        #pragma unroll
        for (int nt = 0; nt < 4; ++nt) {
            const float* br = &sm[P3_ST + (k0 + lx) * 72 + jh * 32 + nt * 8 + ly];
            mma1688(c[nt], a0, a1, a2, a3, FB(br[0]), FB(br[4 * 72]));
        }
    }

    int il = i0 + ly, ih = il + 8;
    #pragma unroll
    for (int nt = 0; nt < 4; ++nt) {
        int jb = jh * 32 + nt * 8 + 2 * lx;
        float2* pl = (float2*)&out[base + il * 64 + jb];
        float2* ph = (float2*)&out[base + ih * 64 + jb];
        float2 cl = *pl, chh = *ph;
        cl.x += c[nt][0]; cl.y += c[nt][1];
        chh.x += c[nt][2]; chh.y += c[nt][3];
        *pl = cl; *ph = chh;
    }
}

extern "C" void kernel_launch(void* const* d_in, const int* in_sizes, int n_in,
                              void* d_out, int out_size)
{
    (void)in_sizes; (void)n_in; (void)out_size;
    const float* r  = (const float*)d_in[0];
    const float* k  = (const float*)d_in[1];
    const float* v  = (const float*)d_in[2];
    const float* w  = (const float*)d_in[3];
    const float* u  = (const float*)d_in[4];
    const float* s0 = (const float*)d_in[5];
    float* out  = (float*)d_out;
    float* outF = out + OUT_ELEMS;

    cudaFuncSetAttribute(rwkv_phase1, cudaFuncAttributeMaxDynamicSharedMemorySize, SMEM1_BYTES);
    cudaFuncSetAttribute(rwkv_phase3, cudaFuncAttributeMaxDynamicSharedMemorySize, SMEM3_BYTES);

    rwkv_phase1<<<BH_ * N_, 512, SMEM1_BYTES>>>(r, k, v, w, u, out);
    rwkv_phase2<<<BH_, 256>>>(s0, outF);
    rwkv_phase3<<<BH_ * N_, 512, SMEM3_BYTES>>>(out);
}

// round 5
// speedup vs baseline: 1.7025x; 1.0316x over previous
#include <cuda_runtime.h>
#include <cstdint>

#define B_ 4
#define H_ 16
#define T_ 2048
#define K_ 64
#define CH_ 128
#define N_ 16
#define BH_ (B_*H_)
#define OUT_ELEMS (B_*H_*T_*K_)
#define LOGMIN (-5.2983174324035645f)

// ---- scratch ----
__device__ float g_rwi[B_*H_*T_*K_];      // r * exp(cum_prev)  (tf32-rounded)
__device__ float g_wkv[BH_*N_*K_*K_];
__device__ float g_states[BH_*N_*K_*K_];
__device__ float g_wse[BH_*N_*K_];

// ---- phase1 smem layout (float offsets) ----
#define O_RW    0        // 128 x 64, stride 68  (8704)   A-operand of MMA1 (= r*exp(cp))
#define O_CUM   8704     // 128 x 64, stride 64  (8192)
#define O_A     0        // 128 x 128, stride 132 (16896) -- aliases RW+CUM after MMA1
#define O_KK    16896    // 128 x 64, stride 76  (9728)   k*exp(-cum); MMA1-B and MMA3-A
#define O_V     26624    // 128 x 64, stride 72  (9216)
#define O_U     35840
#define O_DIAG  35904    // 128
#define O_EWS   36032    // 64
#define O_SEG   36096    // 8 x 64
#define SMEM1_FLOATS 36608
#define SMEM1_BYTES  (SMEM1_FLOATS*4)

__device__ __forceinline__ float f2tf(float x) {
    uint32_t r;
    asm("cvt.rna.tf32.f32 %0, %1;" : "=r"(r) : "f"(x));
    return __uint_as_float(r);
}
__device__ __forceinline__ void mma1688(float* c, uint32_t a0, uint32_t a1, uint32_t a2, uint32_t a3,
                                        uint32_t b0, uint32_t b1) {
    asm volatile("mma.sync.aligned.m16n8k8.row.col.f32.tf32.tf32.f32 "
                 "{%0,%1,%2,%3},{%4,%5,%6,%7},{%8,%9},{%0,%1,%2,%3};"
                 : "+f"(c[0]), "+f"(c[1]), "+f"(c[2]), "+f"(c[3])
                 : "r"(a0), "r"(a1), "r"(a2), "r"(a3), "r"(b0), "r"(b1));
}
#define FB(x) __float_as_uint(x)

__global__ void __launch_bounds__(512)
rwkv_phase1(const float* __restrict__ r, const float* __restrict__ k,
            const float* __restrict__ v, const float* __restrict__ w,
            const float* __restrict__ u, float* __restrict__ out)
{
    extern __shared__ float sm[];
    const int tid = threadIdx.x;
    const int wid = tid >> 5, lid = tid & 31;
    const int ly = lid >> 2, lx = lid & 3;
    const int bhn = blockIdx.x;
    const int bh = bhn >> 4, n = bhn & 15;
    const int h = bh & (H_ - 1);
    const int base = bh * (T_ * K_) + n * (CH_ * K_);

    // ---- pass A: w -> CUM (pre-clipped); v -> V (tf32, stride 72); u ----
    {
        const float4* w4 = (const float4*)(w + base);
        const float4* v4 = (const float4*)(v + base);
        #pragma unroll
        for (int it = 0; it < 4; ++it) {
            int f4 = tid + it * 512;
            int t = f4 >> 4, k0 = (f4 & 15) * 4;
            float4 ww = w4[f4];
            ww.x = fmaxf(ww.x, LOGMIN); ww.y = fmaxf(ww.y, LOGMIN);
            ww.z = fmaxf(ww.z, LOGMIN); ww.w = fmaxf(ww.w, LOGMIN);
            *(float4*)&sm[O_CUM + t * 64 + k0] = ww;
            float4 vv = v4[f4];
            vv.x = f2tf(vv.x); vv.y = f2tf(vv.y); vv.z = f2tf(vv.z); vv.w = f2tf(vv.w);
            *(float4*)&sm[O_V + t * 72 + k0] = vv;
        }
        if (tid < 64) sm[O_U + tid] = u[h * 64 + tid];
    }
    __syncthreads();

    // ---- pass B: segmented cumsum (8 segments x 16 t-rows) ----
    {
        int kq = tid & 63, seg = tid >> 6;
        float run = 0.f;
        #pragma unroll
        for (int tt = 0; tt < 16; ++tt) {
            int idx = (seg * 16 + tt) * 64 + kq;
            run += sm[O_CUM + idx];
            sm[O_CUM + idx] = run;
        }
        sm[O_SEG + seg * 64 + kq] = run;
    }
    __syncthreads();
    {
        int kq = tid & 63, seg = tid >> 6;
        if (seg > 0) {
            float pre = 0.f;
            #pragma unroll
            for (int s = 0; s < 7; ++s)
                if (s < seg) pre += sm[O_SEG + s * 64 + kq];
            #pragma unroll
            for (int tt = 0; tt < 16; ++tt) sm[O_CUM + (seg * 16 + tt) * 64 + kq] += pre;
        }
    }
    __syncthreads();
    if (tid < 64) {
        float ws = sm[O_CUM + 127 * 64 + tid];
        float ews = __expf(ws);
        sm[O_EWS + tid] = ews;
        g_wse[(bh * N_ + n) * K_ + tid] = ews;
    }
    __syncthreads();

    // ---- pass C: rw (stride 68), kk (stride 76), g_rwi, diag ----
    {
        const float4* r4g = (const float4*)(r + base);
        const float4* k4g = (const float4*)(k + base);
        #pragma unroll
        for (int it = 0; it < 4; ++it) {
            int f4 = tid + it * 512;
            int t = f4 >> 4, k0 = (f4 & 15) * 4;
            float4 rv = r4g[f4];
            float4 kv = k4g[f4];
            float4 c4 = *(const float4*)&sm[O_CUM + t * 64 + k0];
            float4 cp4 = (t > 0) ? *(const float4*)&sm[O_CUM + (t - 1) * 64 + k0]
                                 : make_float4(0.f, 0.f, 0.f, 0.f);
            float4 uu = *(const float4*)&sm[O_U + k0];
            float re[4] = {rv.x, rv.y, rv.z, rv.w};
            float ke[4] = {kv.x, kv.y, kv.z, kv.w};
            float ce[4] = {c4.x, c4.y, c4.z, c4.w};
            float cpe[4] = {cp4.x, cp4.y, cp4.z, cp4.w};
            float ue[4] = {uu.x, uu.y, uu.z, uu.w};
            float rwv[4], kkv[4];
            float dpart = 0.f;
            #pragma unroll
            for (int e = 0; e < 4; ++e) {
                rwv[e] = f2tf(re[e] * __expf(cpe[e]));   // r * exp(cum_prev)
                kkv[e] = f2tf(ke[e] * __expf(-ce[e]));   // k * exp(-cum)
                dpart += re[e] * ue[e] * ke[e];
            }
            *(float4*)&sm[O_RW + t * 68 + k0] = make_float4(rwv[0], rwv[1], rwv[2], rwv[3]);
            *(float4*)&sm[O_KK + t * 76 + k0] = make_float4(kkv[0], kkv[1], kkv[2], kkv[3]);
            *(float4*)&g_rwi[base + f4 * 4]   = make_float4(rwv[0], rwv[1], rwv[2], rwv[3]);
            float dv = dpart;
            #pragma unroll
            for (int s = 1; s < 16; s <<= 1) dv += __shfl_xor_sync(0xffffffffu, dv, s, 16);
            if ((tid & 15) == 0) sm[O_DIAG + t] = dv;
        }
    }
    __syncthreads();

    // ---- MMA1: a[128x128] = rw @ kk^T, lower-triangular strips only ----
    const int i0 = (wid & 7) * 16;
    const int jh = wid >> 3;              // 0..1 column half
    // strip nt needed iff jh*64 + nt*8 <= i0+15
    int ntmax = (i0 + 16 - jh * 64) >> 3;
    ntmax = ntmax < 0 ? 0 : (ntmax > 8 ? 8 : ntmax);

    float c1[8][4];
    #pragma unroll
    for (int nt = 0; nt < 8; ++nt)
        #pragma unroll
        for (int e = 0; e < 4; ++e) c1[nt][e] = 0.f;

    #pragma unroll
    for (int ks = 0; ks < 8; ++ks) {
        int k0 = ks * 8;
        const float* ar = &sm[O_RW + (i0 + ly) * 68 + k0 + lx];
        uint32_t a0 = FB(ar[0]), a1 = FB(ar[8 * 68]), a2 = FB(ar[4]), a3 = FB(ar[8 * 68 + 4]);
        #pragma unroll
        for (int nt = 0; nt < 8; ++nt) {
            if (nt < ntmax) {
                const float* br = &sm[O_KK + (jh * 64 + nt * 8 + ly) * 76 + k0 + lx];
                mma1688(c1[nt], a0, a1, a2, a3, FB(br[0]), FB(br[4]));
            }
        }
    }

    // ---- MMA3: wkv[64x64] = kk^T @ v, scaled by ews[row]  (warp: 16x16 tile) ----
    {
        const int i0k = (wid & 3) * 16, j0c = (wid >> 2) * 16;
        float c3[2][4];
        #pragma unroll
        for (int nt = 0; nt < 2; ++nt)
            #pragma unroll
            for (int e = 0; e < 4; ++e) c3[nt][e] = 0.f;
        #pragma unroll
        for (int ks = 0; ks < 16; ++ks) {
            int k0 = ks * 8;
            const float* ac = &sm[O_KK + (k0 + lx) * 76 + i0k + ly];
            uint32_t a0 = FB(ac[0]), a1 = FB(ac[8]), a2 = FB(ac[4 * 76]), a3 = FB(ac[4 * 76 + 8]);
            #pragma unroll
            for (int nt = 0; nt < 2; ++nt) {
                const float* br = &sm[O_V + (k0 + lx) * 72 + j0c + nt * 8 + ly];
                mma1688(c3[nt], a0, a1, a2, a3, FB(br[0]), FB(br[4 * 72]));
            }
        }
        int wb = bhn * (K_ * K_);
        int il = i0k + ly, ih = il + 8;
        float sl = sm[O_EWS + il], sh = sm[O_EWS + ih];
        #pragma unroll
        for (int nt = 0; nt < 2; ++nt) {
            int jb = j0c + nt * 8 + 2 * lx;
            *(float2*)&g_wkv[wb + il * 64 + jb] = make_float2(c3[nt][0] * sl, c3[nt][1] * sl);
            *(float2*)&g_wkv[wb + ih * 64 + jb] = make_float2(c3[nt][2] * sh, c3[nt][3] * sh);
        }
    }
    __syncthreads();   // MMA1/MMA3 reads of RW done before A overwrites

    // ---- epilogue 1: tril(-1) mask + diag, tf32-round, store a (stride 132) ----
    {
        int il = i0 + ly, ih = il + 8;
        float dgl = f2tf(sm[O_DIAG + il]);
        float dgh = f2tf(sm[O_DIAG + ih]);
        #pragma unroll
        for (int nt = 0; nt < 8; ++nt) {
            int jb = jh * 64 + nt * 8 + 2 * lx;
            float v0 = (jb     < il) ? f2tf(c1[nt][0]) : ((jb     == il) ? dgl : 0.f);
            float v1 = (jb + 1 < il) ? f2tf(c1[nt][1]) : ((jb + 1 == il) ? dgl : 0.f);
            float v2 = (jb     < ih) ? f2tf(c1[nt][2]) : ((jb     == ih) ? dgh : 0.f);
            float v3 = (jb + 1 < ih) ? f2tf(c1[nt][3]) : ((jb + 1 == ih) ? dgh : 0.f);
            *(float2*)&sm[O_A + il * 132 + jb] = make_float2(v0, v1);
            *(float2*)&sm[O_A + ih * 132 + jb] = make_float2(v2, v3);
        }
    }
    __syncthreads();

    // ---- MMA2: out[128x64] = a @ v, k-steps bounded by triangle ----
    {
        // rows i0..i0+15 need k <= i0+15  ->  ks < i0/8 + 2
        const int ksmax = (i0 >> 3) + 2;
        float c2[4][4];
        #pragma unroll
        for (int nt = 0; nt < 4; ++nt)
            #pragma unroll
            for (int e = 0; e < 4; ++e) c2[nt][e] = 0.f;
        #pragma unroll
        for (int ks = 0; ks < 16; ++ks) {
            if (ks < ksmax) {
                int k0 = ks * 8;
                const float* ar = &sm[O_A + (i0 + ly) * 132 + k0 + lx];
                uint32_t a0 = FB(ar[0]), a1 = FB(ar[8 * 132]), a2 = FB(ar[4]), a3 = FB(ar[8 * 132 + 4]);
                #pragma unroll
                for (int nt = 0; nt < 4; ++nt) {
                    const float* br = &sm[O_V + (k0 + lx) * 72 + jh * 32 + nt * 8 + ly];
                    mma1688(c2[nt], a0, a1, a2, a3, FB(br[0]), FB(br[4 * 72]));
                }
            }
        }
        int il = i0 + ly, ih = il + 8;
        #pragma unroll
        for (int nt = 0; nt < 4; ++nt) {
            int jb = jh * 32 + nt * 8 + 2 * lx;
            *(float2*)&out[base + il * 64 + jb] = make_float2(c2[nt][0], c2[nt][1]);
            *(float2*)&out[base + ih * 64 + jb] = make_float2(c2[nt][2], c2[nt][3]);
        }
    }
}

// ---- phase 2: sequential scan over chunks per (b,h) ----
__global__ void __launch_bounds__(256, 1)
rwkv_phase2(const float* __restrict__ state0, float* __restrict__ out_final)
{
    const int bh = blockIdx.x;
    const int tid = threadIdx.x;
    float s[16];
    const float* src = state0 + bh * (K_ * K_);
    #pragma unroll
    for (int i = 0; i < 16; ++i) s[i] = src[i * 256 + tid];

    for (int n = 0; n < N_; ++n) {
        const int ob = (bh * N_ + n) * (K_ * K_);
        const int wb = (bh * N_ + n) * K_;
        #pragma unroll
        for (int i = 0; i < 16; ++i) {
            int e = i * 256 + tid;
            g_states[ob + e] = s[i];
            float wse = __ldg(&g_wse[wb + (e >> 6)]);
            s[i] = fmaf(s[i], wse, g_wkv[ob + e]);
        }
    }
    #pragma unroll
    for (int i = 0; i < 16; ++i) out_final[bh * (K_ * K_) + i * 256 + tid] = s[i];
}

// ---- phase 3: out += (r*w_intra) @ states[chunk], tf32 mma, 512 threads ----
#define P3_ST  0          // 64 x 64, stride 72 (4608)
#define P3_RW  4608       // 128 x 64, stride 68 (8704)
#define SMEM3_FLOATS 13312
#define SMEM3_BYTES  (SMEM3_FLOATS * 4)

__global__ void __launch_bounds__(512)
rwkv_phase3(float* __restrict__ out)
{
    extern __shared__ float sm[];
    const int tid = threadIdx.x;
    const int wid = tid >> 5, lid = tid & 31;
    const int ly = lid >> 2, lx = lid & 3;
    const int bhn = blockIdx.x;
    const int bh = bhn >> 4, n = bhn & 15;
    const int base = bh * (T_ * K_) + n * (CH_ * K_);
    const int sb = bhn * (K_ * K_);

    {
        const float4* st4 = (const float4*)(g_states + sb);
        #pragma unroll
        for (int it = 0; it < 2; ++it) {
            int f4 = tid + it * 512;
            int kd = f4 >> 4, j0 = (f4 & 15) * 4;
            float4 sv = st4[f4];
            sv.x = f2tf(sv.x); sv.y = f2tf(sv.y); sv.z = f2tf(sv.z); sv.w = f2tf(sv.w);
            *(float4*)&sm[P3_ST + kd * 72 + j0] = sv;
        }
        const float4* rw4 = (const float4*)(g_rwi + base);
        #pragma unroll
        for (int it = 0; it < 4; ++it) {
            int f4 = tid + it * 512;
            int t = f4 >> 4, k0 = (f4 & 15) * 4;
            *(float4*)&sm[P3_RW + t * 68 + k0] = rw4[f4];   // already tf32-rounded
        }
    }
    __syncthreads();

    const int i0 = (wid & 7) * 16;
    const int jh = wid >> 3;
    float c[4][4];
    #pragma unroll
    for (int nt = 0; nt < 4; ++nt)
        #pragma unroll
        for (int e = 0; e < 4; ++e) c[nt][e] = 0.f;

    #pragma unroll
    for (int ks = 0; ks < 8; ++ks) {
        int k0 = ks * 8;
        const float* ar = &sm[P3_RW + (i0 + ly) * 68 + k0 + lx];
        uint32_t a0 = FB(ar[0]), a1 = FB(ar[8 * 68]), a2 = FB(ar[4]), a3 = FB(ar[8 * 68 + 4]);
        #pragma unroll
        for (int nt = 0; nt < 4; ++nt) {
            const float* br = &sm[P3_ST + (k0 + lx) * 72 + jh * 32 + nt * 8 + ly];
            mma1688(c[nt], a0, a1, a2, a3, FB(br[0]), FB(br[4 * 72]));
        }
    }

    int il = i0 + ly, ih = il + 8;
    #pragma unroll
    for (int nt = 0; nt < 4; ++nt) {
        int jb = jh * 32 + nt * 8 + 2 * lx;
        float2* pl = (float2*)&out[base + il * 64 + jb];
        float2* ph = (float2*)&out[base + ih * 64 + jb];
        float2 cl = *pl, chh = *ph;
        cl.x += c[nt][0]; cl.y += c[nt][1];
        chh.x += c[nt][2]; chh.y += c[nt][3];
        *pl = cl; *ph = chh;
    }
}

extern "C" void kernel_launch(void* const* d_in, const int* in_sizes, int n_in,
                              void* d_out, int out_size)
{
    (void)in_sizes; (void)n_in; (void)out_size;
    const float* r  = (const float*)d_in[0];
    const float* k  = (const float*)d_in[1];
    const float* v  = (const float*)d_in[2];
    const float* w  = (const float*)d_in[3];
    const float* u  = (const float*)d_in[4];
    const float* s0 = (const float*)d_in[5];
    float* out  = (float*)d_out;
    float* outF = out + OUT_ELEMS;

    cudaFuncSetAttribute(rwkv_phase1, cudaFuncAttributeMaxDynamicSharedMemorySize, SMEM1_BYTES);
    cudaFuncSetAttribute(rwkv_phase3, cudaFuncAttributeMaxDynamicSharedMemorySize, SMEM3_BYTES);

    rwkv_phase1<<<BH_ * N_, 512, SMEM1_BYTES>>>(r, k, v, w, u, out);
    rwkv_phase2<<<BH_, 256>>>(s0, outF);
    rwkv_phase3<<<BH_ * N_, 512, SMEM3_BYTES>>>(out);
}

// round 6
// speedup vs baseline: 1.7541x; 1.0303x over previous
#include <cuda_runtime.h>
#include <cstdint>

#define B_ 4
#define H_ 16
#define T_ 2048
#define K_ 64
#define CH_ 128
#define N_ 16
#define BH_ (B_*H_)
#define OUT_ELEMS (B_*H_*T_*K_)
#define LOGMIN (-5.2983174324035645f)

// ---- scratch ----
__device__ float g_rwi[B_*H_*T_*K_];      // r * exp(cum_prev)  (tf32-rounded)
__device__ float g_wkv[BH_*N_*K_*K_];
__device__ float g_states[BH_*N_*K_*K_];
__device__ float g_wse[BH_*N_*K_];

// ---- phase1 smem layout (float offsets) ----
#define O_RW    0        // 128 x 64, stride 68 (8704); after MMA1 reused as partial buf
#define O_CUM   8704     // 128 x 64, stride 64 (8192)
#define O_KK    16896    // 128 x 64, stride 76 (9728)
#define O_V     26624    // 128 x 64, stride 72 (9216)
#define O_U     35840
#define O_DIAG  35904    // 128
#define O_EWS   36032    // 64
#define O_SEG   36096    // 8 x 64
#define SMEM1_FLOATS 36608
#define SMEM1_BYTES  (SMEM1_FLOATS*4)

__device__ __forceinline__ float f2tf(float x) {
    uint32_t r;
    asm("cvt.rna.tf32.f32 %0, %1;" : "=r"(r) : "f"(x));
    return __uint_as_float(r);
}
__device__ __forceinline__ void mma1688(float* c, uint32_t a0, uint32_t a1, uint32_t a2, uint32_t a3,
                                        uint32_t b0, uint32_t b1) {
    asm volatile("mma.sync.aligned.m16n8k8.row.col.f32.tf32.tf32.f32 "
                 "{%0,%1,%2,%3},{%4,%5,%6,%7},{%8,%9},{%0,%1,%2,%3};"
                 : "+f"(c[0]), "+f"(c[1]), "+f"(c[2]), "+f"(c[3])
                 : "r"(a0), "r"(a1), "r"(a2), "r"(a3), "r"(b0), "r"(b1));
}
#define FB(x) __float_as_uint(x)

__global__ void __launch_bounds__(512)
rwkv_phase1(const float* __restrict__ r, const float* __restrict__ k,
            const float* __restrict__ v, const float* __restrict__ w,
            const float* __restrict__ u, float* __restrict__ out)
{
    extern __shared__ float sm[];
    const int tid = threadIdx.x;
    const int wid = tid >> 5, lid = tid & 31;
    const int ly = lid >> 2, lx = lid & 3;
    const int bhn = blockIdx.x;
    const int bh = bhn >> 4, n = bhn & 15;
    const int h = bh & (H_ - 1);
    const int base = bh * (T_ * K_) + n * (CH_ * K_);

    // ---- prefetch r,k into registers (hides DRAM latency behind passes A/B) ----
    float4 pr[4], pk[4];
    {
        const float4* r4g = (const float4*)(r + base);
        const float4* k4g = (const float4*)(k + base);
        #pragma unroll
        for (int it = 0; it < 4; ++it) {
            pr[it] = r4g[tid + it * 512];
            pk[it] = k4g[tid + it * 512];
        }
    }

    // ---- pass A: w -> CUM (pre-clipped); v -> V (tf32, stride 72); u ----
    {
        const float4* w4 = (const float4*)(w + base);
        const float4* v4 = (const float4*)(v + base);
        #pragma unroll
        for (int it = 0; it < 4; ++it) {
            int f4 = tid + it * 512;
            int t = f4 >> 4, k0 = (f4 & 15) * 4;
            float4 ww = w4[f4];
            ww.x = fmaxf(ww.x, LOGMIN); ww.y = fmaxf(ww.y, LOGMIN);
            ww.z = fmaxf(ww.z, LOGMIN); ww.w = fmaxf(ww.w, LOGMIN);
            *(float4*)&sm[O_CUM + t * 64 + k0] = ww;
            float4 vv = v4[f4];
            vv.x = f2tf(vv.x); vv.y = f2tf(vv.y); vv.z = f2tf(vv.z); vv.w = f2tf(vv.w);
            *(float4*)&sm[O_V + t * 72 + k0] = vv;
        }
        if (tid < 64) sm[O_U + tid] = u[h * 64 + tid];
    }
    __syncthreads();

    // ---- pass B1: segmented cumsum (8 segments x 16 t-rows) ----
    {
        int kq = tid & 63, seg = tid >> 6;
        float run = 0.f;
        #pragma unroll
        for (int tt = 0; tt < 16; ++tt) {
            int idx = (seg * 16 + tt) * 64 + kq;
            run += sm[O_CUM + idx];
            sm[O_CUM + idx] = run;
        }
        sm[O_SEG + seg * 64 + kq] = run;
    }
    __syncthreads();

    // ---- pass B2: prefix apply; seg0 threads compute ews in parallel ----
    {
        int kq = tid & 63, seg = tid >> 6;
        if (seg > 0) {
            float pre = 0.f;
            #pragma unroll
            for (int s = 0; s < 7; ++s)
                if (s < seg) pre += sm[O_SEG + s * 64 + kq];
            #pragma unroll
            for (int tt = 0; tt < 16; ++tt) sm[O_CUM + (seg * 16 + tt) * 64 + kq] += pre;
        } else {
            float ws = 0.f;
            #pragma unroll
            for (int s = 0; s < 8; ++s) ws += sm[O_SEG + s * 64 + kq];
            float ews = __expf(ws);
            sm[O_EWS + kq] = ews;
            g_wse[(bh * N_ + n) * K_ + kq] = ews;
        }
    }
    __syncthreads();

    // ---- pass C: rw (stride 68), kk (stride 76), g_rwi, diag ----
    {
        #pragma unroll
        for (int it = 0; it < 4; ++it) {
            int f4 = tid + it * 512;
            int t = f4 >> 4, k0 = (f4 & 15) * 4;
            float4 rv = pr[it];
            float4 kv = pk[it];
            float4 c4 = *(const float4*)&sm[O_CUM + t * 64 + k0];
            float4 cp4 = (t > 0) ? *(const float4*)&sm[O_CUM + (t - 1) * 64 + k0]
                                 : make_float4(0.f, 0.f, 0.f, 0.f);
            float4 uu = *(const float4*)&sm[O_U + k0];
            float re[4] = {rv.x, rv.y, rv.z, rv.w};
            float ke[4] = {kv.x, kv.y, kv.z, kv.w};
            float ce[4] = {c4.x, c4.y, c4.z, c4.w};
            float cpe[4] = {cp4.x, cp4.y, cp4.z, cp4.w};
            float ue[4] = {uu.x, uu.y, uu.z, uu.w};
            float rwv[4], kkv[4];
            float dpart = 0.f;
            #pragma unroll
            for (int e = 0; e < 4; ++e) {
                rwv[e] = f2tf(re[e] * __expf(cpe[e]));   // r * exp(cum_prev)
                kkv[e] = f2tf(ke[e] * __expf(-ce[e]));   // k * exp(-cum)
                dpart += re[e] * ue[e] * ke[e];
            }
            *(float4*)&sm[O_RW + t * 68 + k0] = make_float4(rwv[0], rwv[1], rwv[2], rwv[3]);
            *(float4*)&sm[O_KK + t * 76 + k0] = make_float4(kkv[0], kkv[1], kkv[2], kkv[3]);
            *(float4*)&g_rwi[base + f4 * 4]   = make_float4(rwv[0], rwv[1], rwv[2], rwv[3]);
            float dv = dpart;
            #pragma unroll
            for (int s = 1; s < 16; s <<= 1) dv += __shfl_xor_sync(0xffffffffu, dv, s, 16);
            if ((tid & 15) == 0) sm[O_DIAG + t] = dv;
        }
    }
    __syncthreads();

    // ---- warp mapping: SMSP-balanced triangle ----
    // jh: column half (0: cols 0-63, 1: cols 64-127)
    // blk: row block 0..7, paired (b, 7-b) on same SMSP for equal strip totals
    const int jh = wid >> 3;
    const int widL = wid & 7;
    const int blk = (widL < 4) ? widL : 11 - widL;
    const int i0 = blk * 16;
    int ntmax = (i0 + 16 - jh * 64) >> 3;
    ntmax = ntmax < 0 ? 0 : (ntmax > 8 ? 8 : ntmax);

    // ---- MMA1: a[i0:i0+16, jh*64 + nt*8] strips, accumulators stay in regs ----
    float c1[8][4];
    #pragma unroll
    for (int nt = 0; nt < 8; ++nt)
        #pragma unroll
        for (int e = 0; e < 4; ++e) c1[nt][e] = 0.f;

    #pragma unroll
    for (int ks = 0; ks < 8; ++ks) {
        int k0 = ks * 8;
        const float* ar = &sm[O_RW + (i0 + ly) * 68 + k0 + lx];
        uint32_t a0 = FB(ar[0]), a1 = FB(ar[8 * 68]), a2 = FB(ar[4]), a3 = FB(ar[8 * 68 + 4]);
        #pragma unroll
        for (int nt = 0; nt < 8; ++nt) {
            if (nt < ntmax) {
                const float* br = &sm[O_KK + (jh * 64 + nt * 8 + ly) * 76 + k0 + lx];
                mma1688(c1[nt], a0, a1, a2, a3, FB(br[0]), FB(br[4]));
            }
        }
    }

    // ---- MMA3: wkv[64x64] = kk^T @ v, scaled by ews[row] (warp: 16x16 tile) ----
    {
        const int i0k = (wid & 3) * 16, j0c = (wid >> 2) * 16;
        float c3[2][4];
        #pragma unroll
        for (int nt = 0; nt < 2; ++nt)
            #pragma unroll
            for (int e = 0; e < 4; ++e) c3[nt][e] = 0.f;
        #pragma unroll
        for (int ks = 0; ks < 16; ++ks) {
            int k0 = ks * 8;
            const float* ac = &sm[O_KK + (k0 + lx) * 76 + i0k + ly];
            uint32_t a0 = FB(ac[0]), a1 = FB(ac[8]), a2 = FB(ac[4 * 76]), a3 = FB(ac[4 * 76 + 8]);
            #pragma unroll
            for (int nt = 0; nt < 2; ++nt) {
                const float* br = &sm[O_V + (k0 + lx) * 72 + j0c + nt * 8 + ly];
                mma1688(c3[nt], a0, a1, a2, a3, FB(br[0]), FB(br[4 * 72]));
            }
        }
        int wb = bhn * (K_ * K_);
        int il = i0k + ly, ih = il + 8;
        float sl = sm[O_EWS + il], sh = sm[O_EWS + ih];
        #pragma unroll
        for (int nt = 0; nt < 2; ++nt) {
            int jb = j0c + nt * 8 + 2 * lx;
            *(float2*)&g_wkv[wb + il * 64 + jb] = make_float2(c3[nt][0] * sl, c3[nt][1] * sl);
            *(float2*)&g_wkv[wb + ih * 64 + jb] = make_float2(c3[nt][2] * sh, c3[nt][3] * sh);
        }
    }
    __syncthreads();   // all RW reads done; O_RW region becomes partial buffer

    // ---- mask + in-register C->A conversion + MMA2 (out partials) ----
    float c2[8][4];
    #pragma unroll
    for (int nt = 0; nt < 8; ++nt)
        #pragma unroll
        for (int e = 0; e < 4; ++e) c2[nt][e] = 0.f;

    {
        const int il = i0 + ly, ih = il + 8;
        const int l1 = ly * 4 + (lx >> 1);
        const int l2 = l1 + 2;
        const bool odd = lx & 1;
        #pragma unroll
        for (int nt = 0; nt < 8; ++nt) {
            if (nt < ntmax) {
                int jc = jh * 64 + nt * 8;
                int jcg = jc + 2 * lx;
                // strict lower-triangular mask (diag handled in epilogue), tf32 round
                float m0 = (jcg     < il) ? f2tf(c1[nt][0]) : 0.f;
                float m1 = (jcg + 1 < il) ? f2tf(c1[nt][1]) : 0.f;
                float m2 = (jcg     < ih) ? f2tf(c1[nt][2]) : 0.f;
                float m3 = (jcg + 1 < ih) ? f2tf(c1[nt][3]) : 0.f;
                // C-fragment -> A-fragment (k-step = cols jc..jc+7)
                float t00 = __shfl_sync(0xffffffffu, m0, l1);
                float t01 = __shfl_sync(0xffffffffu, m1, l1);
                float t20 = __shfl_sync(0xffffffffu, m0, l2);
                float t21 = __shfl_sync(0xffffffffu, m1, l2);
                float t10 = __shfl_sync(0xffffffffu, m2, l1);
                float t11 = __shfl_sync(0xffffffffu, m3, l1);
                float t30 = __shfl_sync(0xffffffffu, m2, l2);
                float t31 = __shfl_sync(0xffffffffu, m3, l2);
                uint32_t a0 = FB(odd ? t01 : t00);
                uint32_t a2 = FB(odd ? t21 : t20);
                uint32_t a1 = FB(odd ? t11 : t10);
                uint32_t a3 = FB(odd ? t31 : t30);
                #pragma unroll
                for (int no = 0; no < 8; ++no) {
                    const float* br = &sm[O_V + (jc + lx) * 72 + no * 8 + ly];
                    mma1688(c2[no], a0, a1, a2, a3, FB(br[0]), FB(br[4 * 72]));
                }
            }
        }
    }

    // jh1 warps with work: store partial to reused RW region
    if (jh == 1 && ntmax > 0) {
        float* pb = &sm[O_RW + (blk - 4) * 1088];
        int jb = 2 * lx;
        #pragma unroll
        for (int nt = 0; nt < 8; ++nt) {
            *(float2*)&pb[ly * 68 + nt * 8 + jb]       = make_float2(c2[nt][0], c2[nt][1]);
            *(float2*)&pb[(ly + 8) * 68 + nt * 8 + jb] = make_float2(c2[nt][2], c2[nt][3]);
        }
    }
    __syncthreads();

    // ---- epilogue: jh0 warps combine partials + diag*v, write out ----
    if (jh == 0) {
        const int il = i0 + ly, ih = il + 8;
        const float dgl = sm[O_DIAG + il], dgh = sm[O_DIAG + ih];
        const bool haveP = (blk >= 4);
        const float* pb = &sm[O_RW + (blk - 4) * 1088];
        #pragma unroll
        for (int nt = 0; nt < 8; ++nt) {
            int jb = nt * 8 + 2 * lx;
            float2 pl = make_float2(0.f, 0.f), ph = make_float2(0.f, 0.f);
            if (haveP) {
                pl = *(const float2*)&pb[ly * 68 + jb];
                ph = *(const float2*)&pb[(ly + 8) * 68 + jb];
            }
            float2 vl = *(const float2*)&sm[O_V + il * 72 + jb];
            float2 vh = *(const float2*)&sm[O_V + ih * 72 + jb];
            float o0 = c2[nt][0] + pl.x + dgl * vl.x;
            float o1 = c2[nt][1] + pl.y + dgl * vl.y;
            float o2 = c2[nt][2] + ph.x + dgh * vh.x;
            float o3 = c2[nt][3] + ph.y + dgh * vh.y;
            *(float2*)&out[base + il * 64 + jb] = make_float2(o0, o1);
            *(float2*)&out[base + ih * 64 + jb] = make_float2(o2, o3);
        }
    }
}

// ---- phase 2: sequential scan over chunks per (b,h) ----
__global__ void __launch_bounds__(256, 1)
rwkv_phase2(const float* __restrict__ state0, float* __restrict__ out_final)
{
    const int bh = blockIdx.x;
    const int tid = threadIdx.x;
    float s[16];
    const float* src = state0 + bh * (K_ * K_);
    #pragma unroll
    for (int i = 0; i < 16; ++i) s[i] = src[i * 256 + tid];

    for (int n = 0; n < N_; ++n) {
        const int ob = (bh * N_ + n) * (K_ * K_);
        const int wb = (bh * N_ + n) * K_;
        #pragma unroll
        for (int i = 0; i < 16; ++i) {
            int e = i * 256 + tid;
            g_states[ob + e] = s[i];
            float wse = __ldg(&g_wse[wb + (e >> 6)]);
            s[i] = fmaf(s[i], wse, g_wkv[ob + e]);
        }
    }
    #pragma unroll
    for (int i = 0; i < 16; ++i) out_final[bh * (K_ * K_) + i * 256 + tid] = s[i];
}

// ---- phase 3: out += (r*w_intra) @ states[chunk], tf32 mma, 512 threads ----
#define P3_ST  0          // 64 x 64, stride 72 (4608)
#define P3_RW  4608       // 128 x 64, stride 68 (8704)
#define SMEM3_FLOATS 13312
#define SMEM3_BYTES  (SMEM3_FLOATS * 4)

__global__ void __launch_bounds__(512)
rwkv_phase3(float* __restrict__ out)
{
    extern __shared__ float sm[];
    const int tid = threadIdx.x;
    const int wid = tid >> 5, lid = tid & 31;
    const int ly = lid >> 2, lx = lid & 3;
    const int bhn = blockIdx.x;
    const int bh = bhn >> 4, n = bhn & 15;
    const int base = bh * (T_ * K_) + n * (CH_ * K_);
    const int sb = bhn * (K_ * K_);

    {
        const float4* st4 = (const float4*)(g_states + sb);
        #pragma unroll
        for (int it = 0; it < 2; ++it) {
            int f4 = tid + it * 512;
            int kd = f4 >> 4, j0 = (f4 & 15) * 4;
            float4 sv = st4[f4];
            sv.x = f2tf(sv.x); sv.y = f2tf(sv.y); sv.z = f2tf(sv.z); sv.w = f2tf(sv.w);
            *(float4*)&sm[P3_ST + kd * 72 + j0] = sv;
        }
        const float4* rw4 = (const float4*)(g_rwi + base);
        #pragma unroll
        for (int it = 0; it < 4; ++it) {
            int f4 = tid + it * 512;
            int t = f4 >> 4, k0 = (f4 & 15) * 4;
            *(float4*)&sm[P3_RW + t * 68 + k0] = rw4[f4];   // already tf32-rounded
        }
    }
    __syncthreads();

    const int i0 = (wid & 7) * 16;
    const int jh = wid >> 3;
    float c[4][4];
    #pragma unroll
    for (int nt = 0; nt < 4; ++nt)
        #pragma unroll
        for (int e = 0; e < 4; ++e) c[nt][e] = 0.f;

    #pragma unroll
    for (int ks = 0; ks < 8; ++ks) {
        int k0 = ks * 8;
        const float* ar = &sm[P3_RW + (i0 + ly) * 68 + k0 + lx];
        uint32_t a0 = FB(ar[0]), a1 = FB(ar[8 * 68]), a2 = FB(ar[4]), a3 = FB(ar[8 * 68 + 4]);
        #pragma unroll
        for (int nt = 0; nt < 4; ++nt) {
            const float* br = &sm[P3_ST + (k0 + lx) * 72 + jh * 32 + nt * 8 + ly];
            mma1688(c[nt], a0, a1, a2, a3, FB(br[0]), FB(br[4 * 72]));
        }
    }

    int il = i0 + ly, ih = il + 8;
    #pragma unroll
    for (int nt = 0; nt < 4; ++nt) {
        int jb = jh * 32 + nt * 8 + 2 * lx;
        float2* pl = (float2*)&out[base + il * 64 + jb];
        float2* ph = (float2*)&out[base + ih * 64 + jb];
        float2 cl = *pl, chh = *ph;
        cl.x += c[nt][0]; cl.y += c[nt][1];
        chh.x += c[nt][2]; chh.y += c[nt][3];
        *pl = cl; *ph = chh;
    }
}

extern "C" void kernel_launch(void* const* d_in, const int* in_sizes, int n_in,
                              void* d_out, int out_size)
{
    (void)in_sizes; (void)n_in; (void)out_size;
    const float* r  = (const float*)d_in[0];
    const float* k  = (const float*)d_in[1];
    const float* v  = (const float*)d_in[2];
    const float* w  = (const float*)d_in[3];
    const float* u  = (const float*)d_in[4];
    const float* s0 = (const float*)d_in[5];
    float* out  = (float*)d_out;
    float* outF = out + OUT_ELEMS;

    cudaFuncSetAttribute(rwkv_phase1, cudaFuncAttributeMaxDynamicSharedMemorySize, SMEM1_BYTES);
    cudaFuncSetAttribute(rwkv_phase3, cudaFuncAttributeMaxDynamicSharedMemorySize, SMEM3_BYTES);

    rwkv_phase1<<<BH_ * N_, 512, SMEM1_BYTES>>>(r, k, v, w, u, out);
    rwkv_phase2<<<BH_, 256>>>(s0, outF);
    rwkv_phase3<<<BH_ * N_, 512, SMEM3_BYTES>>>(out);
}